// round 4
// baseline (speedup 1.0000x reference)
#include <cuda_runtime.h>
#include <cuda_bf16.h>
#include <cstdint>
#include <math.h>

#define NUM_TOKENS 8192
#define HIDDEN 4096
#define NUM_EXPERTS 8
#define INTER 2048

// ---------------- device scratch (no allocs allowed) ----------------
__device__ int   g_cnt[NUM_EXPERTS];
__device__ int   g_idx[NUM_EXPERTS * NUM_TOKENS];
__device__ float g_inter[(size_t)NUM_TOKENS * INTER];   // 64 MB

// ---------------- routing ----------------
__global__ void zero_cnt_kernel() {
    if (threadIdx.x < NUM_EXPERTS) g_cnt[threadIdx.x] = 0;
}

// Token ids may arrive as int32 or int64 depending on harness dtype handling.
// int64 ids in [0, 32000) have zero high words; random int32 ids at odd
// positions are essentially never all zero. Detect once per block (reads only
// the first 128 bytes — safe under either layout).
__global__ void route_kernel(const int* __restrict__ tok32) {
    __shared__ int s_is32;
    if (threadIdx.x == 0) {
        int any = 0;
        #pragma unroll
        for (int j = 1; j < 32; j += 2) any |= tok32[j];
        s_is32 = (any != 0);
    }
    __syncthreads();
    int i = blockIdx.x * blockDim.x + threadIdx.x;
    if (i < NUM_TOKENS) {
        int e;
        if (s_is32) {
            e = tok32[i] & 7;
        } else {
            long long t = ((const long long*)tok32)[i];
            e = (int)(t & 7);
        }
        int slot = atomicAdd(&g_cnt[e], 1);
        g_idx[e * NUM_TOKENS + slot] = i;
    }
}

// ---------------- helpers ----------------
__device__ __forceinline__ uint32_t cvt_tf32(float f) {
    uint32_t r;
    asm("cvt.rna.tf32.f32 %0, %1;" : "=r"(r) : "f"(f));
    return r;
}

__device__ __forceinline__ void cp16(uint32_t dst, const void* src, bool pred) {
    int sz = pred ? 16 : 0;
    asm volatile("cp.async.cg.shared.global [%0], [%1], 16, %2;\n"
                 :: "r"(dst), "l"(src), "r"(sz));
}
__device__ __forceinline__ void cp_commit() { asm volatile("cp.async.commit_group;\n"); }
__device__ __forceinline__ void cp_wait1()  { asm volatile("cp.async.wait_group 1;\n"); }

__device__ __forceinline__ void mma_tf32(float& c0, float& c1, float& c2, float& c3,
                                         uint32_t a0, uint32_t a1, uint32_t a2, uint32_t a3,
                                         uint32_t b0, uint32_t b1) {
    asm volatile("mma.sync.aligned.m16n8k8.row.col.f32.tf32.tf32.f32 "
                 "{%0,%1,%2,%3}, {%4,%5,%6,%7}, {%8,%9}, {%0,%1,%2,%3};\n"
                 : "+f"(c0), "+f"(c1), "+f"(c2), "+f"(c3)
                 : "r"(a0), "r"(a1), "r"(a2), "r"(a3), "r"(b0), "r"(b1));
}

// ======================================================================
// GEMM1: gu = X_gathered @ W1[e]  (K=4096), fused silu(gate)*up -> g_inter
// Block tile: 128 (m) x 64 (gate n) + 64 (matching up n). BK=32.
// 256 threads = 8 warps: warp_m in {0,1} (64 rows), warp_n in {0..3} (16 cols).
// ======================================================================
#define G1_AST 36      // A smem row stride (floats): 32 + 4 pad
#define G1_BST 72      // B smem row stride (floats): 64 + 8 pad
#define G1_STAGE (128 * G1_AST + 2 * 32 * G1_BST)   // 9216 floats / stage
#define G1_SMEM_BYTES ((2 * G1_STAGE + 128) * 4)    // + 128 ints ridx

__global__ __launch_bounds__(256) void gemm1_kernel(const float* __restrict__ x,
                                                    const float* __restrict__ w1) {
    extern __shared__ float sm[];
    int* ridx = (int*)(sm + 2 * G1_STAGE);

    const int e   = blockIdx.z;
    const int cnt = g_cnt[e];
    const int m0  = blockIdx.y * 128;
    if (m0 >= cnt) return;
    const int n0  = blockIdx.x * 64;

    const int tid = threadIdx.x;
    if (tid < 128) {
        int m = m0 + tid;
        ridx[tid] = (m < cnt) ? g_idx[e * NUM_TOKENS + m] : -1;
    }
    __syncthreads();

    const float* W = w1 + (size_t)e * HIDDEN * (2 * INTER);

    const int wid = tid >> 5, lane = tid & 31;
    const int warp_m = wid & 1, warp_n = wid >> 1;
    const int gid = lane >> 2, tig = lane & 3;

    float cg[4][2][4], cu[4][2][4];
    #pragma unroll
    for (int a = 0; a < 4; a++)
        #pragma unroll
        for (int b = 0; b < 2; b++)
            #pragma unroll
            for (int c = 0; c < 4; c++) { cg[a][b][c] = 0.f; cu[a][b][c] = 0.f; }

    // per-thread A load coords: 4 x float4
    int a_row[4], a_kv[4]; const float* a_src[4]; bool a_pred[4];
    #pragma unroll
    for (int t = 0; t < 4; t++) {
        int vec = tid + t * 256;
        a_row[t] = vec >> 3; a_kv[t] = vec & 7;
        int r = ridx[a_row[t]];
        a_pred[t] = (r >= 0);
        a_src[t] = x + (size_t)(a_pred[t] ? r : 0) * HIDDEN + a_kv[t] * 4;
    }

    uint32_t smem_base = (uint32_t)__cvta_generic_to_shared(sm);

    auto prefetch = [&](int kt, int buf) {
        int k0 = kt * 32;
        #pragma unroll
        for (int t = 0; t < 4; t++)
            cp16(smem_base + (buf * G1_STAGE + a_row[t] * G1_AST + a_kv[t] * 4) * 4,
                 a_src[t] + k0, a_pred[t]);
        #pragma unroll
        for (int t = 0; t < 2; t++) {
            int vec = tid + t * 256;
            int kr = vec >> 4, nv = vec & 15;
            const float* wsrc = W + (size_t)(k0 + kr) * (2 * INTER) + n0 + nv * 4;
            cp16(smem_base + (buf * G1_STAGE + 128 * G1_AST + kr * G1_BST + nv * 4) * 4,
                 wsrc, true);
            cp16(smem_base + (buf * G1_STAGE + 128 * G1_AST + 32 * G1_BST + kr * G1_BST + nv * 4) * 4,
                 wsrc + INTER, true);
        }
    };

    auto compute = [&](int buf) {
        const float* As = sm + buf * G1_STAGE;
        const float* Bg = As + 128 * G1_AST;
        const float* Bu = Bg + 32 * G1_BST;
        #pragma unroll
        for (int ks = 0; ks < 4; ks++) {
            uint32_t a[4][4];
            #pragma unroll
            for (int mt = 0; mt < 4; mt++) {
                int r0 = warp_m * 64 + mt * 16 + gid;
                int c0 = ks * 8 + tig;
                a[mt][0] = cvt_tf32(As[r0 * G1_AST + c0]);
                a[mt][1] = cvt_tf32(As[(r0 + 8) * G1_AST + c0]);
                a[mt][2] = cvt_tf32(As[r0 * G1_AST + c0 + 4]);
                a[mt][3] = cvt_tf32(As[(r0 + 8) * G1_AST + c0 + 4]);
            }
            uint32_t bg[2][2], bu[2][2];
            #pragma unroll
            for (int nt = 0; nt < 2; nt++) {
                int n = warp_n * 16 + nt * 8 + gid;
                int k = ks * 8 + tig;
                bg[nt][0] = cvt_tf32(Bg[k * G1_BST + n]);
                bg[nt][1] = cvt_tf32(Bg[(k + 4) * G1_BST + n]);
                bu[nt][0] = cvt_tf32(Bu[k * G1_BST + n]);
                bu[nt][1] = cvt_tf32(Bu[(k + 4) * G1_BST + n]);
            }
            #pragma unroll
            for (int mt = 0; mt < 4; mt++)
                #pragma unroll
                for (int nt = 0; nt < 2; nt++) {
                    mma_tf32(cg[mt][nt][0], cg[mt][nt][1], cg[mt][nt][2], cg[mt][nt][3],
                             a[mt][0], a[mt][1], a[mt][2], a[mt][3], bg[nt][0], bg[nt][1]);
                    mma_tf32(cu[mt][nt][0], cu[mt][nt][1], cu[mt][nt][2], cu[mt][nt][3],
                             a[mt][0], a[mt][1], a[mt][2], a[mt][3], bu[nt][0], bu[nt][1]);
                }
        }
    };

    const int NK = HIDDEN / 32;   // 128
    prefetch(0, 0);
    cp_commit();
    for (int kt = 0; kt < NK; kt++) {
        int buf = kt & 1;
        if (kt + 1 < NK) prefetch(kt + 1, buf ^ 1);
        cp_commit();
        cp_wait1();
        __syncthreads();
        compute(buf);
        __syncthreads();
    }

    // epilogue: silu(gate) * up -> g_inter[token][col]
    #pragma unroll
    for (int mt = 0; mt < 4; mt++) {
        int lm = warp_m * 64 + mt * 16 + gid;
        int t0 = ridx[lm];
        int t1 = ridx[lm + 8];
        #pragma unroll
        for (int nt = 0; nt < 2; nt++) {
            int col = n0 + warp_n * 16 + nt * 8 + 2 * tig;
            if (t0 >= 0) {
                float g0 = cg[mt][nt][0], u0 = cu[mt][nt][0];
                float g1 = cg[mt][nt][1], u1 = cu[mt][nt][1];
                float2 v;
                v.x = g0 / (1.f + __expf(-g0)) * u0;
                v.y = g1 / (1.f + __expf(-g1)) * u1;
                *(float2*)&g_inter[(size_t)t0 * INTER + col] = v;
            }
            if (t1 >= 0) {
                float g0 = cg[mt][nt][2], u0 = cu[mt][nt][2];
                float g1 = cg[mt][nt][3], u1 = cu[mt][nt][3];
                float2 v;
                v.x = g0 / (1.f + __expf(-g0)) * u0;
                v.y = g1 / (1.f + __expf(-g1)) * u1;
                *(float2*)&g_inter[(size_t)t1 * INTER + col] = v;
            }
        }
    }
}

// ======================================================================
// GEMM2: out = inter_gathered @ W2[e]  (K=2048), scatter rows to out.
// Block tile 128 x 128, BK=32. warp_m in {0,1}, warp_n in {0..3} (32 cols).
// ======================================================================
#define G2_AST 36
#define G2_BST 136     // 128 + 8 pad
#define G2_STAGE (128 * G2_AST + 32 * G2_BST)       // 4608 + 4352 = 8960 floats
#define G2_SMEM_BYTES ((2 * G2_STAGE + 128) * 4)

__global__ __launch_bounds__(256) void gemm2_kernel(const float* __restrict__ w2,
                                                    float* __restrict__ out) {
    extern __shared__ float sm[];
    int* ridx = (int*)(sm + 2 * G2_STAGE);

    const int e   = blockIdx.z;
    const int cnt = g_cnt[e];
    const int m0  = blockIdx.y * 128;
    if (m0 >= cnt) return;
    const int n0  = blockIdx.x * 128;

    const int tid = threadIdx.x;
    if (tid < 128) {
        int m = m0 + tid;
        ridx[tid] = (m < cnt) ? g_idx[e * NUM_TOKENS + m] : -1;
    }
    __syncthreads();

    const float* W = w2 + (size_t)e * INTER * HIDDEN;

    const int wid = tid >> 5, lane = tid & 31;
    const int warp_m = wid & 1, warp_n = wid >> 1;
    const int gid = lane >> 2, tig = lane & 3;

    float cc[4][4][4];
    #pragma unroll
    for (int a = 0; a < 4; a++)
        #pragma unroll
        for (int b = 0; b < 4; b++)
            #pragma unroll
            for (int c = 0; c < 4; c++) cc[a][b][c] = 0.f;

    int a_row[4], a_kv[4]; const float* a_src[4]; bool a_pred[4];
    #pragma unroll
    for (int t = 0; t < 4; t++) {
        int vec = tid + t * 256;
        a_row[t] = vec >> 3; a_kv[t] = vec & 7;
        int r = ridx[a_row[t]];
        a_pred[t] = (r >= 0);
        a_src[t] = g_inter + (size_t)(a_pred[t] ? r : 0) * INTER + a_kv[t] * 4;
    }

    uint32_t smem_base = (uint32_t)__cvta_generic_to_shared(sm);

    auto prefetch = [&](int kt, int buf) {
        int k0 = kt * 32;
        #pragma unroll
        for (int t = 0; t < 4; t++)
            cp16(smem_base + (buf * G2_STAGE + a_row[t] * G2_AST + a_kv[t] * 4) * 4,
                 a_src[t] + k0, a_pred[t]);
        #pragma unroll
        for (int t = 0; t < 4; t++) {
            int vec = tid + t * 256;
            int kr = vec >> 5, nv = vec & 31;
            cp16(smem_base + (buf * G2_STAGE + 128 * G2_AST + kr * G2_BST + nv * 4) * 4,
                 W + (size_t)(k0 + kr) * HIDDEN + n0 + nv * 4, true);
        }
    };

    auto compute = [&](int buf) {
        const float* As = sm + buf * G2_STAGE;
        const float* Bs = As + 128 * G2_AST;
        #pragma unroll
        for (int ks = 0; ks < 4; ks++) {
            uint32_t a[4][4];
            #pragma unroll
            for (int mt = 0; mt < 4; mt++) {
                int r0 = warp_m * 64 + mt * 16 + gid;
                int c0 = ks * 8 + tig;
                a[mt][0] = cvt_tf32(As[r0 * G2_AST + c0]);
                a[mt][1] = cvt_tf32(As[(r0 + 8) * G2_AST + c0]);
                a[mt][2] = cvt_tf32(As[r0 * G2_AST + c0 + 4]);
                a[mt][3] = cvt_tf32(As[(r0 + 8) * G2_AST + c0 + 4]);
            }
            uint32_t b[4][2];
            #pragma unroll
            for (int nt = 0; nt < 4; nt++) {
                int n = warp_n * 32 + nt * 8 + gid;
                int k = ks * 8 + tig;
                b[nt][0] = cvt_tf32(Bs[k * G2_BST + n]);
                b[nt][1] = cvt_tf32(Bs[(k + 4) * G2_BST + n]);
            }
            #pragma unroll
            for (int mt = 0; mt < 4; mt++)
                #pragma unroll
                for (int nt = 0; nt < 4; nt++)
                    mma_tf32(cc[mt][nt][0], cc[mt][nt][1], cc[mt][nt][2], cc[mt][nt][3],
                             a[mt][0], a[mt][1], a[mt][2], a[mt][3], b[nt][0], b[nt][1]);
        }
    };

    const int NK = INTER / 32;   // 64
    prefetch(0, 0);
    cp_commit();
    for (int kt = 0; kt < NK; kt++) {
        int buf = kt & 1;
        if (kt + 1 < NK) prefetch(kt + 1, buf ^ 1);
        cp_commit();
        cp_wait1();
        __syncthreads();
        compute(buf);
        __syncthreads();
    }

    // epilogue: scatter to out
    #pragma unroll
    for (int mt = 0; mt < 4; mt++) {
        int lm = warp_m * 64 + mt * 16 + gid;
        int t0 = ridx[lm];
        int t1 = ridx[lm + 8];
        #pragma unroll
        for (int nt = 0; nt < 4; nt++) {
            int col = n0 + warp_n * 32 + nt * 8 + 2 * tig;
            if (t0 >= 0) {
                float2 v = make_float2(cc[mt][nt][0], cc[mt][nt][1]);
                *(float2*)&out[(size_t)t0 * HIDDEN + col] = v;
            }
            if (t1 >= 0) {
                float2 v = make_float2(cc[mt][nt][2], cc[mt][nt][3]);
                *(float2*)&out[(size_t)t1 * HIDDEN + col] = v;
            }
        }
    }
}

// ---------------- launch ----------------
extern "C" void kernel_launch(void* const* d_in, const int* in_sizes, int n_in,
                              void* d_out, int out_size) {
    // Bind inputs by unique element counts (robust to metadata ordering):
    //   token_ids: 8192, x: 8192*4096, gate_up: 8*4096*4096, down: 8*2048*4096
    const float* x  = nullptr;
    const float* w1 = nullptr;
    const float* w2 = nullptr;
    const int*   tok = nullptr;
    for (int i = 0; i < n_in; i++) {
        long long n = in_sizes[i];
        if (n == (long long)NUM_TOKENS) tok = (const int*)d_in[i];
        else if (n == (long long)NUM_TOKENS * HIDDEN) x = (const float*)d_in[i];
        else if (n == (long long)NUM_EXPERTS * HIDDEN * 2 * INTER) w1 = (const float*)d_in[i];
        else if (n == (long long)NUM_EXPERTS * INTER * HIDDEN) w2 = (const float*)d_in[i];
    }
    float* out = (float*)d_out;

    cudaFuncSetAttribute(gemm1_kernel, cudaFuncAttributeMaxDynamicSharedMemorySize, G1_SMEM_BYTES);
    cudaFuncSetAttribute(gemm2_kernel, cudaFuncAttributeMaxDynamicSharedMemorySize, G2_SMEM_BYTES);

    zero_cnt_kernel<<<1, 32>>>();
    route_kernel<<<NUM_TOKENS / 256, 256>>>(tok);

    // gemm1: n-tiles (2048/64=32) x m-tiles (8192/128=64) x experts(8)
    gemm1_kernel<<<dim3(32, 64, 8), 256, G1_SMEM_BYTES>>>(x, w1);
    // gemm2: n-tiles (4096/128=32) x m-tiles (64) x experts(8)
    gemm2_kernel<<<dim3(32, 64, 8), 256, G2_SMEM_BYTES>>>(w2, out);
}